// round 5
// baseline (speedup 1.0000x reference)
#include <cuda_runtime.h>

#define T_STEPS 512
#define BATCH   64
#define DIN     256
#define DH      1024
#define DOUT    256
#define BH      (BATCH * DH)      // 65536
#define SCAN_CTAS 128

typedef unsigned long long ull;

// Scratch (device globals: allocation-free per harness rules)
__device__ float g_xp[T_STEPS * BH];       // [T][B][H] input projection
__device__ float g_hs[T_STEPS * BH];       // [T][B][H] hidden states
__device__ unsigned int g_barG[T_STEPS * 4 * 32]; // per-(step,rowgroup) counters, 128B apart

// ---- packed f32x2 helpers -------------------------------------------------
__device__ __forceinline__ ull pack2(float x) {
    ull r;
    asm("mov.b64 %0, {%1, %1};" : "=l"(r) : "f"(x));
    return r;
}
__device__ __forceinline__ ull pack2v(float lo, float hi) {
    ull r;
    asm("mov.b64 %0, {%1, %2};" : "=l"(r) : "f"(lo), "f"(hi));
    return r;
}
__device__ __forceinline__ void fma2(ull& acc, ull a, ull b) {
    asm("fma.rn.f32x2 %0, %1, %2, %0;" : "+l"(acc) : "l"(a), "l"(b));
}
__device__ __forceinline__ void unpack2(ull v, float& lo, float& hi) {
    asm("mov.b64 {%0, %1}, %2;" : "=f"(lo), "=f"(hi) : "l"(v));
}

// ---------------------------------------------------------------------------
// Kernel A: x_proj[t][b][h] = sum_i inputs[b][t][i] * W_in[i][h] + bias[h]
// ---------------------------------------------------------------------------
__global__ void k_xproj(const float* __restrict__ x,
                        const float* __restrict__ Wi,
                        const float* __restrict__ bias) {
    const int t  = blockIdx.x;
    const int n0 = blockIdx.y * 64;
    __shared__ __align__(16) float As[64][36];
    __shared__ __align__(16) float Bs[32][68];
    const int tid = threadIdx.x;
    const int ty = tid >> 4, tx = tid & 15;
    ull acc[4][2] = {};

    for (int k0 = 0; k0 < DIN; k0 += 32) {
        for (int i = tid; i < 64 * 32; i += 256) {
            int m = i >> 5, kk = i & 31;
            As[m][kk] = x[(m * T_STEPS + t) * DIN + k0 + kk];
        }
        for (int i = tid; i < 32 * 64; i += 256) {
            int kk = i >> 6, n = i & 63;
            Bs[kk][n] = Wi[(k0 + kk) * DH + n0 + n];
        }
        __syncthreads();
#pragma unroll
        for (int kk = 0; kk < 32; kk++) {
            ulonglong2 bb = *(const ulonglong2*)&Bs[kk][tx * 4];
#pragma unroll
            for (int i = 0; i < 4; i++) {
                ull pa = pack2(As[ty * 4 + i][kk]);
                fma2(acc[i][0], pa, bb.x);
                fma2(acc[i][1], pa, bb.y);
            }
        }
        __syncthreads();
    }
    float4 bv = *(const float4*)&bias[n0 + tx * 4];
#pragma unroll
    for (int i = 0; i < 4; i++) {
        float4 v;
        unpack2(acc[i][0], v.x, v.y);
        unpack2(acc[i][1], v.z, v.w);
        v.x += bv.x; v.y += bv.y; v.z += bv.z; v.w += bv.w;
        *(float4*)&g_xp[t * BH + (ty * 4 + i) * DH + n0 + tx * 4] = v;
    }
}

// ---------------------------------------------------------------------------
// Kernel B: persistent scan, K-split warps.
// 128 CTAs x 256 thr. CTA (rb=bid>>5, cb=bid&31): rows rb*16..+16,
// cols cb*32..+32. Warp w owns K-slice [128w,128w+128) for ALL 32 cols;
// lane = one column, W column in 64 packed f32x2 regs.
// h rows staged ONCE per step into SMEM (64KB, 16 LDG.128/thread), consumed
// via broadcast LDS. Partials reduced through SMEM. 4 independent row-group
// chains, each with its own 32-CTA barrier.
// ---------------------------------------------------------------------------
__device__ __forceinline__ void group_barrier(int t, int rb, int cb) {
    __syncthreads();
    if (threadIdx.x == 0) {
        unsigned int* ctr = &g_barG[(t * 4 + rb) * 32];
        __threadfence();
        atomicAdd(ctr, 1u);
        while (*(volatile unsigned int*)ctr < 32u) { }
        __threadfence();
        if (cb == 0 && t > 0) g_barG[((t - 1) * 4 + rb) * 32] = 0;
    }
    __syncthreads();
}

__global__ void __launch_bounds__(256, 1) k_scan(const float* __restrict__ Wh) {
    extern __shared__ __align__(16) float smem[];
    float* sH = smem;                    // [16][1024]  staged h rows (64KB)
    float* sP = smem + 16 * 1024;       // [8][512]    warp partials (16KB)

    const int tid  = threadIdx.x;
    const int w    = tid >> 5;
    const int lane = tid & 31;
    const int rb   = blockIdx.x >> 5;          // 0..3 row group
    const int cb   = blockIdx.x & 31;          // 0..31 col block
    const int row0 = rb * 16;
    const int col  = cb * 32 + lane;           // this lane's output column
    const int k0   = w * 128;                  // warp's K slice

    if (cb == 0 && tid == 0) g_barG[((T_STEPS - 1) * 4 + rb) * 32] = 0;

    // W column in registers: W2[u] = (Wh[k0+2u][col], Wh[k0+2u+1][col])
    ull W2[64];
#pragma unroll
    for (int u = 0; u < 64; u++) {
        float w0 = Wh[(k0 + 2 * u) * DH + col];
        float w1 = Wh[(k0 + 2 * u + 1) * DH + col];
        W2[u] = pack2v(w0, w1);
    }

    // Output mapping for t=0 and reductions: thread -> 2 outputs (o, o+1)
    const int o    = tid * 2;                  // 0..510
    const int orow = row0 + (o >> 5);
    const int ocol = cb * 32 + (o & 31);

    // t = 0: h = tanh(xp)
    {
        float2 xv = *(const float2*)&g_xp[orow * DH + ocol];
        float2 hv;
        hv.x = tanhf(xv.x);
        hv.y = tanhf(xv.y);
        *(float2*)&g_hs[orow * DH + ocol] = hv;
    }
    group_barrier(0, rb, cb);

    for (int t = 1; t < T_STEPS; t++) {
        // prefetch xp for this step (independent of h)
        float2 xv = *(const float2*)&g_xp[t * BH + orow * DH + ocol];

        // stage h[t-1] rows [row0, row0+16) x 1024 into SMEM, coalesced
        {
            const float4* src = (const float4*)(g_hs + (t - 1) * BH + row0 * DH);
            float4* dst = (float4*)sH;
#pragma unroll
            for (int q = 0; q < 16; q++) {
                dst[q * 256 + tid] = src[q * 256 + tid];
            }
        }
        __syncthreads();

        // each warp: K-slice dot for its 32 cols x 16 rows
        ull acc[16];
#pragma unroll
        for (int r = 0; r < 16; r++) acc[r] = 0ull;

#pragma unroll
        for (int r = 0; r < 16; r++) {
            const ulonglong2* hp = (const ulonglong2*)(sH + r * 1024 + k0);
#pragma unroll
            for (int u = 0; u < 32; u++) {
                ulonglong2 hv = hp[u];           // broadcast LDS.128
                fma2(acc[r], hv.x, W2[2 * u]);
                fma2(acc[r], hv.y, W2[2 * u + 1]);
            }
        }

        // write this warp's partials: sP[w][r*32+lane]
#pragma unroll
        for (int r = 0; r < 16; r++) {
            float lo, hi;
            unpack2(acc[r], lo, hi);
            sP[w * 512 + r * 32 + lane] = lo + hi;
        }
        __syncthreads();

        // reduce 8 warp partials; each thread produces 2 adjacent outputs
        float2 s = {0.f, 0.f};
#pragma unroll
        for (int ww = 0; ww < 8; ww++) {
            float2 v = *(const float2*)&sP[ww * 512 + o];
            s.x += v.x;
            s.y += v.y;
        }
        float2 hv;
        hv.x = tanhf(xv.x + s.x);
        hv.y = tanhf(xv.y + s.y);
        *(float2*)&g_hs[t * BH + orow * DH + ocol] = hv;

        group_barrier(t, rb, cb);
    }
}

// ---------------------------------------------------------------------------
// Kernel C: out[b][t][o] = sum_h hs[t][b][h] * W_out[h][o] + bias[o]
// ---------------------------------------------------------------------------
__global__ void k_out(const float* __restrict__ Wo,
                      const float* __restrict__ bias,
                      float* __restrict__ out) {
    const int t  = blockIdx.x;
    const int n0 = blockIdx.y * 64;
    __shared__ __align__(16) float As[64][36];
    __shared__ __align__(16) float Bs[32][68];
    const int tid = threadIdx.x;
    const int ty = tid >> 4, tx = tid & 15;
    ull acc[4][2] = {};

    for (int k0 = 0; k0 < DH; k0 += 32) {
        for (int i = tid; i < 64 * 32; i += 256) {
            int m = i >> 5, kk = i & 31;
            As[m][kk] = g_hs[t * BH + m * DH + k0 + kk];
        }
        for (int i = tid; i < 32 * 64; i += 256) {
            int kk = i >> 6, n = i & 63;
            Bs[kk][n] = Wo[(k0 + kk) * DOUT + n0 + n];
        }
        __syncthreads();
#pragma unroll
        for (int kk = 0; kk < 32; kk++) {
            ulonglong2 bb = *(const ulonglong2*)&Bs[kk][tx * 4];
#pragma unroll
            for (int i = 0; i < 4; i++) {
                ull pa = pack2(As[ty * 4 + i][kk]);
                fma2(acc[i][0], pa, bb.x);
                fma2(acc[i][1], pa, bb.y);
            }
        }
        __syncthreads();
    }
    float4 bv = *(const float4*)&bias[n0 + tx * 4];
#pragma unroll
    for (int i = 0; i < 4; i++) {
        float4 v;
        unpack2(acc[i][0], v.x, v.y);
        unpack2(acc[i][1], v.z, v.w);
        v.x += bv.x; v.y += bv.y; v.z += bv.z; v.w += bv.w;
        *(float4*)&out[((ty * 4 + i) * T_STEPS + t) * DOUT + n0 + tx * 4] = v;
    }
}

// ---------------------------------------------------------------------------
extern "C" void kernel_launch(void* const* d_in, const int* in_sizes, int n_in,
                              void* d_out, int out_size) {
    const float* x  = (const float*)d_in[0];  // inputs [B,T,DIN]
    const float* Wi = (const float*)d_in[1];  // input_kernel [DIN,DH]
    const float* Wh = (const float*)d_in[2];  // hidden_kernel [DH,DH]
    const float* bh = (const float*)d_in[3];  // hidden_bias [DH]
    const float* Wo = (const float*)d_in[4];  // output_kernel [DH,DOUT]
    const float* bo = (const float*)d_in[5];  // output_bias [DOUT]
    float* out = (float*)d_out;               // [B,T,DOUT]

    const int scan_smem = (16 * 1024 + 8 * 512) * (int)sizeof(float); // 81920 B
    cudaFuncSetAttribute(k_scan, cudaFuncAttributeMaxDynamicSharedMemorySize,
                         scan_smem);

    k_xproj<<<dim3(T_STEPS, DH / 64), 256>>>(x, Wi, bh);
    k_scan<<<SCAN_CTAS, 256, scan_smem>>>(Wh);
    k_out<<<dim3(T_STEPS, DOUT / 64), 256>>>(Wo, bo, out);
}